// round 14
// baseline (speedup 1.0000x reference)
#include <cuda_runtime.h>
#include <cuda_fp16.h>
#include <mma.h>
#include <cstdint>
#include <cstddef>

using namespace nvcuda;

#define N_NODES 50000
#define D 128
#define E_EDGES 800000
#define FULL_TILES (N_NODES / 128)                       // 390
#define TAIL_ROW0 (FULL_TILES * 128)                     // 49920
#define TAIL_ROWS (N_NODES - TAIL_ROW0)                  // 80

// fused kernel shared layout (dynamic): A tile only
#define LDA 264                                          // 256 + 8 pad (halves)
#define SM_TOTAL (128 * LDA * 2)                         // 67584 (>= 128*128*4 for tail staging)

// Scratch (no allocations allowed in kernel_launch).
// NOTE: d_deg relies on zero-init at module load; scan_all_kernel re-zeroes it
// after consuming, so every graph replay sees zeroed counters (deterministic).
__device__ float  d_h[(size_t)N_NODES * D];
__device__ int    d_deg[N_NODES];
__device__ int    d_rowptr[N_NODES + 1];
__device__ int    d_cursor[N_NODES + 1];
__device__ int    d_adj[E_EDGES];
__device__ __half d_wt1h[128 * 256];     // fp16 [n][k] (wmma B)
__device__ __half d_wt2h[128 * 256];
__device__ float  d_brep1[16 * 128];     // bias replicated 16 rows (accumulator init)
__device__ float  d_brep2[16 * 128];

// ---------------------------------------------------------------------------
// prep: fp16 weights [n][k] + replicated bias tiles + degree count (d_deg pre-zeroed)
__global__ void prep_kernel(const float* __restrict__ Wl1, const float* __restrict__ Wr1,
                            const float* __restrict__ Wl2, const float* __restrict__ Wr2,
                            const float* __restrict__ bl1, const float* __restrict__ bl2,
                            const int* __restrict__ dst) {
    int stride = gridDim.x * blockDim.x;
    int i0 = blockIdx.x * blockDim.x + threadIdx.x;
    for (int i = i0; i < 128 * 256; i += stride) {
        int n = i >> 8;          // 0..127
        int k = i & 255;         // 0..255
        float v1, v2;
        if (k < 128) {
            v1 = Wl1[n * 128 + k];
            v2 = Wl2[n * 128 + k];
        } else {
            v1 = Wr1[n * 128 + (k - 128)];
            v2 = Wr2[n * 128 + (k - 128)];
        }
        d_wt1h[i] = __float2half(v1);
        d_wt2h[i] = __float2half(v2);
    }
    for (int i = i0; i < 16 * 128; i += stride) {
        d_brep1[i] = bl1[i & 127];
        d_brep2[i] = bl2[i & 127];
    }
    for (int e = i0; e < E_EDGES; e += stride) {
        atomicAdd(&d_deg[dst[e]], 1);
    }
}

// Whole prefix scan in ONE block (1024 threads, 49 chunks, carried offset).
// Writes rowptr[i+1] and cursor[i+1]; resets d_deg[i]=0 for the next replay.
__global__ void __launch_bounds__(1024) scan_all_kernel() {
    __shared__ int wsum[32];
    __shared__ int carry_sh;
    int tid = threadIdx.x;
    int lane = tid & 31;
    int warp = tid >> 5;
    if (tid == 0) {
        carry_sh = 0;
        d_rowptr[0] = 0;
        d_cursor[0] = 0;
    }
    __syncthreads();

    const int CHUNKS = (N_NODES + 1023) / 1024;   // 49
    for (int it = 0; it < CHUNKS; it++) {
        int i = it * 1024 + tid;
        int v = 0;
        if (i < N_NODES) {
            v = d_deg[i];
            d_deg[i] = 0;                // reset for next graph replay
        }
        int s = v;
#pragma unroll
        for (int off = 1; off < 32; off <<= 1) {
            int t = __shfl_up_sync(0xffffffffu, s, off);
            if (lane >= off) s += t;
        }
        if (lane == 31) wsum[warp] = s;
        __syncthreads();
        if (warp == 0) {
            int w = wsum[lane];
#pragma unroll
            for (int off = 1; off < 32; off <<= 1) {
                int t = __shfl_up_sync(0xffffffffu, w, off);
                if (lane >= off) w += t;
            }
            wsum[lane] = w;
        }
        __syncthreads();
        int incl = s + (warp > 0 ? wsum[warp - 1] : 0) + carry_sh;
        if (i < N_NODES) {
            d_rowptr[i + 1] = incl;
            d_cursor[i + 1] = incl;
        }
        __syncthreads();                 // everyone has read carry_sh
        if (tid == 1023) carry_sh = incl;
        __syncthreads();
    }
}

__global__ void fill_kernel(const int* __restrict__ src, const int* __restrict__ dst) {
    int stride = gridDim.x * blockDim.x;
    for (int e = blockIdx.x * blockDim.x + threadIdx.x; e < E_EDGES; e += stride) {
        int d = dst[e];
        int p = atomicAdd(&d_cursor[d], 1);
        d_adj[p] = src[e];
    }
}

// ---------------------------------------------------------------------------
// Fused aggregate + wmma fp16 GEMM, 391 blocks:
//   As[m][0:128]   = fp16(mean of neighbor rows of node block_row0+m)   (gather fused)
//   As[m][128:256] = fp16(xin[block_row0+m])
//   D[128,128] = As @ Bh^T + bias;  B fragments from global; block 390 = guarded tail.
__global__ void __launch_bounds__(256) gemm_fused_kernel(const float* __restrict__ x,
                                                         float* __restrict__ outp,
                                                         int layer) {
    extern __shared__ char smem[];
    const float* __restrict__ xin  = (layer == 0) ? x : d_h;
    float* __restrict__ out        = (layer == 0) ? d_h : outp;
    const __half* __restrict__ wth = (layer == 0) ? d_wt1h : d_wt2h;
    const float* __restrict__ brep = (layer == 0) ? d_brep1 : d_brep2;

    __half (*As)[LDA] = (__half(*)[LDA])smem;

    int tid = threadIdx.x;
    int wid = tid >> 5;
    int lane = tid & 31;
    int warp_m = (wid & 3) * 32;     // 0,32,64,96
    int warp_n = (wid >> 2) * 64;    // 0,64
    int block_row0 = blockIdx.x * 128;
    size_t feat = (size_t)lane * 4;

    // ---- fused gather: warp w aggregates rows [w*16, w*16+16) into As[:, 0:128] ----
    for (int rr = 0; rr < 16; rr++) {
        int m = (wid << 4) + rr;
        int gr = block_row0 + m;
        int grc = (gr < N_NODES) ? gr : (N_NODES - 1);
        int base = d_rowptr[grc];
        int end  = d_rowptr[grc + 1];
        int deg  = end - base;

        float4 acc = make_float4(0.f, 0.f, 0.f, 0.f);
        for (int i = base; i < end; i += 32) {
            int cnt = min(32, end - i);
            int sidx = (lane < cnt) ? __ldg(d_adj + i + lane) : 0;
            int j = 0;
            for (; j + 4 <= cnt; j += 4) {
                int s0 = __shfl_sync(0xffffffffu, sidx, j);
                int s1 = __shfl_sync(0xffffffffu, sidx, j + 1);
                int s2 = __shfl_sync(0xffffffffu, sidx, j + 2);
                int s3 = __shfl_sync(0xffffffffu, sidx, j + 3);
                float4 v0 = *(const float4*)(xin + (size_t)s0 * D + feat);
                float4 v1 = *(const float4*)(xin + (size_t)s1 * D + feat);
                float4 v2 = *(const float4*)(xin + (size_t)s2 * D + feat);
                float4 v3 = *(const float4*)(xin + (size_t)s3 * D + feat);
                acc.x += (v0.x + v1.x) + (v2.x + v3.x);
                acc.y += (v0.y + v1.y) + (v2.y + v3.y);
                acc.z += (v0.z + v1.z) + (v2.z + v3.z);
                acc.w += (v0.w + v1.w) + (v2.w + v3.w);
            }
            for (; j < cnt; j++) {
                int s = __shfl_sync(0xffffffffu, sidx, j);
                float4 v = *(const float4*)(xin + (size_t)s * D + feat);
                acc.x += v.x; acc.y += v.y; acc.z += v.z; acc.w += v.w;
            }
        }
        float sc = 1.0f / fmaxf((float)deg, 1.0f);
        __half2 h0 = __floats2half2_rn(acc.x * sc, acc.y * sc);
        __half2 h1 = __floats2half2_rn(acc.z * sc, acc.w * sc);
        uint2 u;
        u.x = *(uint32_t*)&h0;
        u.y = *(uint32_t*)&h1;
        *(uint2*)&As[m][lane * 4] = u;
    }

    // ---- stage self-features: As[:, 128:256] = fp16(xin rows) ----
    for (int idx = tid; idx < 128 * 32; idx += 256) {
        int m = idx >> 5;
        int kq = (idx & 31) * 4;
        int gr = block_row0 + m;
        int grc = (gr < N_NODES) ? gr : (N_NODES - 1);
        float4 v = *(const float4*)(xin + (size_t)grc * D + kq);
        __half2 p0 = __floats2half2_rn(v.x, v.y);
        __half2 p1 = __floats2half2_rn(v.z, v.w);
        uint2 u;
        u.x = *(uint32_t*)&p0;
        u.y = *(uint32_t*)&p1;
        *(uint2*)&As[m][128 + kq] = u;
    }
    __syncthreads();

    // ---- accumulators initialized to bias (from replicated global tile) ----
    wmma::fragment<wmma::accumulator, 16, 16, 16, float> c[2][4];
#pragma unroll
    for (int i = 0; i < 2; i++)
#pragma unroll
        for (int j = 0; j < 4; j++)
            wmma::load_matrix_sync(c[i][j], brep + warp_n + j * 16, 128,
                                   wmma::mem_row_major);

    // ---- mainloop: 16 k-steps, A from shared, B from global ----
#pragma unroll
    for (int k0 = 0; k0 < 256; k0 += 16) {
        wmma::fragment<wmma::matrix_a, 16, 16, 16, __half, wmma::row_major> a[2];
        wmma::fragment<wmma::matrix_b, 16, 16, 16, __half, wmma::col_major> b[4];
#pragma unroll
        for (int i = 0; i < 2; i++)
            wmma::load_matrix_sync(a[i], &As[warp_m + i * 16][k0], LDA);
#pragma unroll
        for (int j = 0; j < 4; j++)
            wmma::load_matrix_sync(b[j], wth + (size_t)(warp_n + j * 16) * 256 + k0, 256);
#pragma unroll
        for (int i = 0; i < 2; i++)
#pragma unroll
            for (int j = 0; j < 4; j++)
                wmma::mma_sync(c[i][j], a[i], b[j], c[i][j]);
    }

    if (blockIdx.x < FULL_TILES) {
        // full tile: direct store
#pragma unroll
        for (int i = 0; i < 2; i++)
#pragma unroll
            for (int j = 0; j < 4; j++)
                wmma::store_matrix_sync(
                    out + (size_t)(block_row0 + warp_m + i * 16) * D + warp_n + j * 16,
                    c[i][j], D, wmma::mem_row_major);
    } else {
        // tail: stage through shared (reusing A space), guarded copy
        __syncthreads();             // done reading As
        float* stg = (float*)smem;   // 128x128 floats = 64KB <= 67.5KB
#pragma unroll
        for (int i = 0; i < 2; i++)
#pragma unroll
            for (int j = 0; j < 4; j++)
                wmma::store_matrix_sync(stg + (size_t)(warp_m + i * 16) * 128 + warp_n + j * 16,
                                        c[i][j], 128, wmma::mem_row_major);
        __syncthreads();
        for (int idx = tid; idx < TAIL_ROWS * 32; idx += 256) {
            int r = idx >> 5;
            int cq = (idx & 31) * 4;
            float4 v = *(float4*)(stg + r * 128 + cq);
            *(float4*)(out + (size_t)(TAIL_ROW0 + r) * D + cq) = v;
        }
    }
}

// ---------------------------------------------------------------------------
extern "C" void kernel_launch(void* const* d_in, const int* in_sizes, int n_in,
                              void* d_out, int out_size) {
    const float* x   = (const float*)d_in[0];
    const int*   ei  = (const int*)d_in[1];
    const float* Wl1 = (const float*)d_in[2];
    const float* bl1 = (const float*)d_in[3];
    const float* Wr1 = (const float*)d_in[4];
    const float* Wl2 = (const float*)d_in[5];
    const float* bl2 = (const float*)d_in[6];
    const float* Wr2 = (const float*)d_in[7];
    float* out = (float*)d_out;

    const int* src = ei;
    const int* dst = ei + E_EDGES;

    cudaFuncSetAttribute(gemm_fused_kernel, cudaFuncAttributeMaxDynamicSharedMemorySize, SM_TOTAL);

    // ---- CSR build + weight/bias prep (d_deg zeroed by scan of previous replay) ----
    prep_kernel<<<1024, 256>>>(Wl1, Wr1, Wl2, Wr2, bl1, bl2, dst);
    scan_all_kernel<<<1, 1024>>>();
    fill_kernel<<<(E_EDGES + 511) / 512, 256>>>(src, dst);

    // ---- layer 1 (aggregate + GEMM fused) ----
    gemm_fused_kernel<<<FULL_TILES + 1, 256, SM_TOTAL>>>(x, nullptr, 0);

    // ---- layer 2 ----
    gemm_fused_kernel<<<FULL_TILES + 1, 256, SM_TOTAL>>>(x, out, 1);
}

// round 15
// speedup vs baseline: 1.4306x; 1.4306x over previous
#include <cuda_runtime.h>
#include <cuda_fp16.h>
#include <mma.h>
#include <cstdint>
#include <cstddef>

using namespace nvcuda;

#define N_NODES 50000
#define D 128
#define E_EDGES 800000
#define FULL_TILES (N_NODES / 128)                       // 390
#define TAIL_ROW0 (FULL_TILES * 128)                     // 49920
#define TAIL_ROWS (N_NODES - TAIL_ROW0)                  // 80

// wmma kernel shared layout (dynamic): A tile only
#define LDA 264                                          // 256 + 8 pad (halves)
#define SM_TOTAL (128 * LDA * 2)                         // 67584 (>= 128*128*4 for tail staging)

// Scratch (no allocations allowed in kernel_launch).
// d_deg relies on zero-init at module load; scan_all_kernel re-zeroes it after
// consuming, so every graph replay sees zeroed counters (deterministic work).
__device__ float  d_agg[(size_t)N_NODES * D];
__device__ float  d_h[(size_t)N_NODES * D];
__device__ int    d_deg[N_NODES];
__device__ int    d_rowptr[N_NODES + 1];
__device__ int    d_adj[E_EDGES];
__device__ int    d_slot[E_EDGES];       // edge's rank within its dst bucket
__device__ __half d_wt1h[128 * 256];     // fp16 [n][k] (wmma B)
__device__ __half d_wt2h[128 * 256];
__device__ float  d_brep1[16 * 128];     // bias replicated 16 rows (accumulator init)
__device__ float  d_brep2[16 * 128];

// ---------------------------------------------------------------------------
// prep: fp16 weights [n][k] + replicated bias tiles + degree count with slot record
__global__ void prep_kernel(const float* __restrict__ Wl1, const float* __restrict__ Wr1,
                            const float* __restrict__ Wl2, const float* __restrict__ Wr2,
                            const float* __restrict__ bl1, const float* __restrict__ bl2,
                            const int* __restrict__ dst) {
    int stride = gridDim.x * blockDim.x;
    int i0 = blockIdx.x * blockDim.x + threadIdx.x;
    for (int i = i0; i < 128 * 256; i += stride) {
        int n = i >> 8;          // 0..127
        int k = i & 255;         // 0..255
        float v1, v2;
        if (k < 128) {
            v1 = Wl1[n * 128 + k];
            v2 = Wl2[n * 128 + k];
        } else {
            v1 = Wr1[n * 128 + (k - 128)];
            v2 = Wr2[n * 128 + (k - 128)];
        }
        d_wt1h[i] = __float2half(v1);
        d_wt2h[i] = __float2half(v2);
    }
    for (int i = i0; i < 16 * 128; i += stride) {
        d_brep1[i] = bl1[i & 127];
        d_brep2[i] = bl2[i & 127];
    }
    for (int e = i0; e < E_EDGES; e += stride) {
        d_slot[e] = atomicAdd(&d_deg[dst[e]], 1);
    }
}

// Whole prefix scan in ONE block (1024 threads, 49 chunks, carried offset).
// Writes rowptr[i+1]; resets d_deg[i]=0 for the next graph replay.
__global__ void __launch_bounds__(1024) scan_all_kernel() {
    __shared__ int wsum[32];
    __shared__ int carry_sh;
    int tid = threadIdx.x;
    int lane = tid & 31;
    int warp = tid >> 5;
    if (tid == 0) {
        carry_sh = 0;
        d_rowptr[0] = 0;
    }
    __syncthreads();

    const int CHUNKS = (N_NODES + 1023) / 1024;   // 49
    for (int it = 0; it < CHUNKS; it++) {
        int i = it * 1024 + tid;
        int v = 0;
        if (i < N_NODES) {
            v = d_deg[i];
            d_deg[i] = 0;                // reset for next graph replay
        }
        int s = v;
#pragma unroll
        for (int off = 1; off < 32; off <<= 1) {
            int t = __shfl_up_sync(0xffffffffu, s, off);
            if (lane >= off) s += t;
        }
        if (lane == 31) wsum[warp] = s;
        __syncthreads();
        if (warp == 0) {
            int w = wsum[lane];
#pragma unroll
            for (int off = 1; off < 32; off <<= 1) {
                int t = __shfl_up_sync(0xffffffffu, w, off);
                if (lane >= off) w += t;
            }
            wsum[lane] = w;
        }
        __syncthreads();
        int incl = s + (warp > 0 ? wsum[warp - 1] : 0) + carry_sh;
        if (i < N_NODES) d_rowptr[i + 1] = incl;
        __syncthreads();                 // everyone has read carry_sh
        if (tid == 1023) carry_sh = incl;
        __syncthreads();
    }
}

// Atomic-free fill: slot was recorded during counting.
__global__ void fill_kernel(const int* __restrict__ src, const int* __restrict__ dst) {
    int stride = gridDim.x * blockDim.x;
    for (int e = blockIdx.x * blockDim.x + threadIdx.x; e < E_EDGES; e += stride) {
        int d = dst[e];
        d_adj[d_rowptr[d] + d_slot[e]] = src[e];
    }
}

// One warp per node: sum neighbor fp32 rows, scale by 1/deg, store (R12-proven).
__global__ void __launch_bounds__(256) gather_kernel(const float* __restrict__ x, int layer) {
    const float* __restrict__ xin = (layer == 0) ? x : d_h;
    int gid = blockIdx.x * blockDim.x + threadIdx.x;
    int n = gid >> 5;
    if (n >= N_NODES) return;
    int lane = gid & 31;
    int base = d_rowptr[n];
    int end  = d_rowptr[n + 1];
    int deg  = end - base;
    size_t feat = (size_t)lane * 4;

    float4 acc = make_float4(0.f, 0.f, 0.f, 0.f);
    for (int i = base; i < end; i += 32) {
        int cnt = min(32, end - i);
        int sidx = (lane < cnt) ? __ldg(d_adj + i + lane) : 0;
        int j = 0;
        for (; j + 4 <= cnt; j += 4) {
            int s0 = __shfl_sync(0xffffffffu, sidx, j);
            int s1 = __shfl_sync(0xffffffffu, sidx, j + 1);
            int s2 = __shfl_sync(0xffffffffu, sidx, j + 2);
            int s3 = __shfl_sync(0xffffffffu, sidx, j + 3);
            float4 v0 = *(const float4*)(xin + (size_t)s0 * D + feat);
            float4 v1 = *(const float4*)(xin + (size_t)s1 * D + feat);
            float4 v2 = *(const float4*)(xin + (size_t)s2 * D + feat);
            float4 v3 = *(const float4*)(xin + (size_t)s3 * D + feat);
            acc.x += (v0.x + v1.x) + (v2.x + v3.x);
            acc.y += (v0.y + v1.y) + (v2.y + v3.y);
            acc.z += (v0.z + v1.z) + (v2.z + v3.z);
            acc.w += (v0.w + v1.w) + (v2.w + v3.w);
        }
        for (; j < cnt; j++) {
            int s = __shfl_sync(0xffffffffu, sidx, j);
            float4 v = *(const float4*)(xin + (size_t)s * D + feat);
            acc.x += v.x; acc.y += v.y; acc.z += v.z; acc.w += v.w;
        }
    }
    float sc = 1.0f / fmaxf((float)deg, 1.0f);
    acc.x *= sc; acc.y *= sc; acc.z *= sc; acc.w *= sc;
    *(float4*)(d_agg + (size_t)n * D + feat) = acc;
}

// ---------------------------------------------------------------------------
// wmma fp16 GEMM, 391 blocks: D[128,128] = Ah[128,256] @ Bh[128,256]^T + bias
// A staged fp32->fp16 in shared; B fragments straight from global (L1-resident);
// bias via accumulator init from replicated global tile; block 390 = guarded tail.
// (R12-proven form.)
__global__ void __launch_bounds__(256) gemm_wmma_kernel(const float* __restrict__ x,
                                                        float* __restrict__ outp,
                                                        int layer) {
    extern __shared__ char smem[];
    const float* __restrict__ xin  = (layer == 0) ? x : d_h;
    float* __restrict__ out        = (layer == 0) ? d_h : outp;
    const __half* __restrict__ wth = (layer == 0) ? d_wt1h : d_wt2h;
    const float* __restrict__ brep = (layer == 0) ? d_brep1 : d_brep2;

    __half (*As)[LDA] = (__half(*)[LDA])smem;

    int tid = threadIdx.x;
    int wid = tid >> 5;
    int warp_m = (wid & 3) * 32;     // 0,32,64,96
    int warp_n = (wid >> 2) * 64;    // 0,64
    int block_row0 = blockIdx.x * 128;

    // ---- stage A: fp32 [agg|xin] -> fp16 shared (row clamp covers tail) ----
    for (int idx = tid; idx < 128 * 64; idx += 256) {
        int m = idx >> 6;
        int kq = (idx & 63) * 4;
        int gr = block_row0 + m;
        int grc = (gr < N_NODES) ? gr : (N_NODES - 1);
        const float* srcp = (kq < 128) ? (d_agg + (size_t)grc * D + kq)
                                       : (xin + (size_t)grc * D + (kq - 128));
        float4 v = *(const float4*)srcp;
        __half2 p0 = __floats2half2_rn(v.x, v.y);
        __half2 p1 = __floats2half2_rn(v.z, v.w);
        uint2 u;
        u.x = *(uint32_t*)&p0;
        u.y = *(uint32_t*)&p1;
        *(uint2*)&As[m][kq] = u;
    }
    __syncthreads();

    // ---- accumulators initialized to bias (from replicated global tile) ----
    wmma::fragment<wmma::accumulator, 16, 16, 16, float> c[2][4];
#pragma unroll
    for (int i = 0; i < 2; i++)
#pragma unroll
        for (int j = 0; j < 4; j++)
            wmma::load_matrix_sync(c[i][j], brep + warp_n + j * 16, 128,
                                   wmma::mem_row_major);

    // ---- mainloop: 16 k-steps, A from shared, B from global ----
#pragma unroll
    for (int k0 = 0; k0 < 256; k0 += 16) {
        wmma::fragment<wmma::matrix_a, 16, 16, 16, __half, wmma::row_major> a[2];
        wmma::fragment<wmma::matrix_b, 16, 16, 16, __half, wmma::col_major> b[4];
#pragma unroll
        for (int i = 0; i < 2; i++)
            wmma::load_matrix_sync(a[i], &As[warp_m + i * 16][k0], LDA);
#pragma unroll
        for (int j = 0; j < 4; j++)
            wmma::load_matrix_sync(b[j], wth + (size_t)(warp_n + j * 16) * 256 + k0, 256);
#pragma unroll
        for (int i = 0; i < 2; i++)
#pragma unroll
            for (int j = 0; j < 4; j++)
                wmma::mma_sync(c[i][j], a[i], b[j], c[i][j]);
    }

    if (blockIdx.x < FULL_TILES) {
        // full tile: direct store
#pragma unroll
        for (int i = 0; i < 2; i++)
#pragma unroll
            for (int j = 0; j < 4; j++)
                wmma::store_matrix_sync(
                    out + (size_t)(block_row0 + warp_m + i * 16) * D + warp_n + j * 16,
                    c[i][j], D, wmma::mem_row_major);
    } else {
        // tail: stage through shared (reusing A space), guarded copy
        __syncthreads();             // done reading As
        float* stg = (float*)smem;   // 128x128 floats = 64KB <= 67.5KB
#pragma unroll
        for (int i = 0; i < 2; i++)
#pragma unroll
            for (int j = 0; j < 4; j++)
                wmma::store_matrix_sync(stg + (size_t)(warp_m + i * 16) * 128 + warp_n + j * 16,
                                        c[i][j], 128, wmma::mem_row_major);
        __syncthreads();
        for (int idx = tid; idx < TAIL_ROWS * 32; idx += 256) {
            int r = idx >> 5;
            int cq = (idx & 31) * 4;
            float4 v = *(float4*)(stg + r * 128 + cq);
            *(float4*)(out + (size_t)(TAIL_ROW0 + r) * D + cq) = v;
        }
    }
}

// ---------------------------------------------------------------------------
extern "C" void kernel_launch(void* const* d_in, const int* in_sizes, int n_in,
                              void* d_out, int out_size) {
    const float* x   = (const float*)d_in[0];
    const int*   ei  = (const int*)d_in[1];
    const float* Wl1 = (const float*)d_in[2];
    const float* bl1 = (const float*)d_in[3];
    const float* Wr1 = (const float*)d_in[4];
    const float* Wl2 = (const float*)d_in[5];
    const float* bl2 = (const float*)d_in[6];
    const float* Wr2 = (const float*)d_in[7];
    float* out = (float*)d_out;

    const int* src = ei;
    const int* dst = ei + E_EDGES;

    const int gather_blocks = (N_NODES * 32 + 255) / 256;

    cudaFuncSetAttribute(gemm_wmma_kernel, cudaFuncAttributeMaxDynamicSharedMemorySize, SM_TOTAL);

    // ---- CSR build + weight/bias prep (d_deg zeroed by scan of previous replay) ----
    prep_kernel<<<1024, 256>>>(Wl1, Wr1, Wl2, Wr2, bl1, bl2, dst);
    scan_all_kernel<<<1, 1024>>>();
    fill_kernel<<<(E_EDGES + 511) / 512, 256>>>(src, dst);

    // ---- layer 1 ----
    gather_kernel<<<gather_blocks, 256>>>(x, 0);
    gemm_wmma_kernel<<<FULL_TILES + 1, 256, SM_TOTAL>>>(x, nullptr, 0);

    // ---- layer 2 ----
    gather_kernel<<<gather_blocks, 256>>>(x, 1);
    gemm_wmma_kernel<<<FULL_TILES + 1, 256, SM_TOTAL>>>(x, out, 1);
}